// round 1
// baseline (speedup 1.0000x reference)
#include <cuda_runtime.h>
#include <cstddef>

#define BB 8
#define HH 128
#define WW 128
#define CC 64
#define FF 128
#define KT 9            // K*K taps
#define OC 18           // 2*KT offset channels
#define SC 576          // KT*CC sampled channels
#define NPIX (BB*HH*WW) // 131072

// Scratch (allocation-free rule: __device__ globals)
__device__ float g_offsets[(size_t)NPIX * OC];                 // ~9.4 MB
__device__ float g_sampled[(size_t)NPIX * SC];                 // ~302 MB

// ---------------------------------------------------------------------------
// Kernel 1: offset conv  (3x3, C=64 -> 18, SAME padding)
// One thread per pixel; W_off cached in smem (41.5 KB), broadcast LDS reads.
// ---------------------------------------------------------------------------
__global__ __launch_bounds__(256) void offset_conv_kernel(
    const float* __restrict__ x, const float* __restrict__ Woff,
    const float* __restrict__ boff)
{
    __shared__ float sW[3 * 3 * CC * OC];
    __shared__ float sB[OC];
    int tid = threadIdx.x;
    for (int i = tid; i < 3 * 3 * CC * OC; i += 256) sW[i] = Woff[i];
    if (tid < OC) sB[tid] = boff[tid];
    __syncthreads();

    int p = blockIdx.x * 256 + tid;           // exactly NPIX threads
    int b = p >> 14;
    int h = (p >> 7) & 127;
    int w = p & 127;

    float acc[OC];
#pragma unroll
    for (int o = 0; o < OC; o++) acc[o] = sB[o];

    for (int ky = 0; ky < 3; ky++) {
        int y = h + ky - 1;
        if ((unsigned)y >= HH) continue;
        for (int kx = 0; kx < 3; kx++) {
            int xx = w + kx - 1;
            if ((unsigned)xx >= WW) continue;
            const float* xp = x + (((size_t)(b * HH + y) * WW + xx) * CC);
            const float* wp = sW + (ky * 3 + kx) * CC * OC;
            for (int c = 0; c < CC; c += 4) {
                float4 v = *(const float4*)(xp + c);
#pragma unroll
                for (int o = 0; o < OC; o++) {
                    acc[o] += v.x * wp[(c + 0) * OC + o]
                            + v.y * wp[(c + 1) * OC + o]
                            + v.z * wp[(c + 2) * OC + o]
                            + v.w * wp[(c + 3) * OC + o];
                }
            }
        }
    }
    float* op = g_offsets + (size_t)p * OC;
#pragma unroll
    for (int o = 0; o < OC; o++) op[o] = acc[o];
}

// ---------------------------------------------------------------------------
// Kernel 2: bilinear deformable sampling
// One warp per (pixel, tap); lane handles 2 channels (float2, coalesced).
// Replicates reference exactly: clip loc, floor, clip corners, weights from
// CLIPPED corner coords (so the boundary-degenerate zeros match).
// ---------------------------------------------------------------------------
__global__ __launch_bounds__(256) void sample_kernel(const float* __restrict__ x)
{
    int gw = blockIdx.x * 8 + (threadIdx.x >> 5);
    int lane = threadIdx.x & 31;
    int p = gw / KT;
    int tap = gw - p * KT;
    if (p >= NPIX) return;

    int b = p >> 14;
    int h = (p >> 7) & 127;
    int w = p & 127;

    float offx = __ldg(&g_offsets[(size_t)p * OC + tap * 2 + 0]);
    float offy = __ldg(&g_offsets[(size_t)p * OC + tap * 2 + 1]);

    // tap grid 'xy': kx = lin[tap%3], ky = lin[tap/3], lin = {-1,0,1}
    float lx = (float)w + (float)(tap % 3) - 1.0f + offx;
    float ly = (float)h + (float)(tap / 3) - 1.0f + offy;
    lx = fminf(fmaxf(lx, 0.0f), (float)(WW - 1));
    ly = fminf(fmaxf(ly, 0.0f), (float)(HH - 1));

    float x0f = floorf(lx);                       // already in [0,127]
    float y0f = floorf(ly);
    float x1f = fminf(x0f + 1.0f, (float)(WW - 1));
    float y1f = fminf(y0f + 1.0f, (float)(HH - 1));

    float wa = (x1f - lx) * (y1f - ly);
    float wb = (x1f - lx) * (ly - y0f);
    float wc = (lx - x0f) * (y1f - ly);
    float wd = (lx - x0f) * (ly - y0f);

    int x0 = (int)x0f, x1 = (int)x1f, y0 = (int)y0f, y1 = (int)y1f;

    int c = lane * 2;
    const float* xb = x + (size_t)b * HH * WW * CC + c;
    float2 Ia = *(const float2*)(xb + ((size_t)y0 * WW + x0) * CC);
    float2 Ib = *(const float2*)(xb + ((size_t)y1 * WW + x0) * CC);
    float2 Ic = *(const float2*)(xb + ((size_t)y0 * WW + x1) * CC);
    float2 Id = *(const float2*)(xb + ((size_t)y1 * WW + x1) * CC);

    float2 s;
    s.x = wa * Ia.x + wb * Ib.x + wc * Ic.x + wd * Id.x;
    s.y = wa * Ia.y + wb * Ib.y + wc * Ic.y + wd * Id.y;
    *(float2*)(g_sampled + (size_t)p * SC + tap * CC + c) = s;
}

// ---------------------------------------------------------------------------
// Kernel 3: final 3x3 conv, 576 -> 128 channels (implicit GEMM)
// One block per (b,h) image row: M=128 pixels x N=128 filters, K=9*576.
// 256 threads, 8x8 register tile, K-chunk 16, SAME padding predicated in the
// A load.
// ---------------------------------------------------------------------------
__global__ __launch_bounds__(256) void final_conv_kernel(
    const float* __restrict__ Wt, const float* __restrict__ bias,
    float* __restrict__ out)
{
    __shared__ float As[16][132];   // [k][pixel], padded (row = 528B, 16B-aligned)
    __shared__ float Bs[16][128];   // [k][f]

    int tid = threadIdx.x;
    int row = blockIdx.x;           // b*128 + h
    int b = row >> 7;
    int h = row & 127;
    int tx = tid & 15;              // f tile: f = tx*8 .. tx*8+7
    int ty = tid >> 4;              // pixel tile: w = ty*8 .. ty*8+7

    float acc[8][8];
#pragma unroll
    for (int i = 0; i < 8; i++)
#pragma unroll
        for (int j = 0; j < 8; j++) acc[i][j] = 0.0f;

    const float* srow_base = g_sampled + (size_t)b * HH * WW * SC;

    for (int ky = 0; ky < 3; ky++) {
        int y = h + ky - 1;
        bool yok = (unsigned)y < HH;
        const float* arow = srow_base + (size_t)y * WW * SC;
        for (int kx = 0; kx < 3; kx++) {
            const float* wbase = Wt + (size_t)((ky * 3 + kx) * SC) * FF;
            for (int kc = 0; kc < SC; kc += 16) {
                // ---- load A tile (128 px x 16 k), transposed into As[k][m]
#pragma unroll
                for (int r = 0; r < 2; r++) {
                    int idx = tid + r * 256;     // 0..511
                    int m = idx >> 2;            // pixel 0..127
                    int kq = idx & 3;            // which float4 of the 16 k's
                    int ws = m + kx - 1;
                    float4 v = make_float4(0.f, 0.f, 0.f, 0.f);
                    if (yok && (unsigned)ws < WW)
                        v = *(const float4*)(arow + (size_t)ws * SC + kc + kq * 4);
                    As[kq * 4 + 0][m] = v.x;
                    As[kq * 4 + 1][m] = v.y;
                    As[kq * 4 + 2][m] = v.z;
                    As[kq * 4 + 3][m] = v.w;
                }
                // ---- load B tile (16 k x 128 f), fully coalesced
#pragma unroll
                for (int r = 0; r < 2; r++) {
                    int rr = (tid >> 5) + r * 8;
                    int f4 = (tid & 31) * 4;
                    *(float4*)&Bs[rr][f4] =
                        *(const float4*)(wbase + (size_t)(kc + rr) * FF + f4);
                }
                __syncthreads();
                // ---- 8x8 outer product, 16 k steps
#pragma unroll
                for (int kk = 0; kk < 16; kk++) {
                    float4 a0 = *(const float4*)&As[kk][ty * 8];
                    float4 a1 = *(const float4*)&As[kk][ty * 8 + 4];
                    float4 b0 = *(const float4*)&Bs[kk][tx * 8];
                    float4 b1 = *(const float4*)&Bs[kk][tx * 8 + 4];
                    float av[8] = {a0.x, a0.y, a0.z, a0.w, a1.x, a1.y, a1.z, a1.w};
                    float bv[8] = {b0.x, b0.y, b0.z, b0.w, b1.x, b1.y, b1.z, b1.w};
#pragma unroll
                    for (int i = 0; i < 8; i++)
#pragma unroll
                        for (int j = 0; j < 8; j++)
                            acc[i][j] += av[i] * bv[j];
                }
                __syncthreads();
            }
        }
    }

    // ---- epilogue: + bias, write NHWC float4s
    float bv[8];
#pragma unroll
    for (int j = 0; j < 8; j++) bv[j] = __ldg(&bias[tx * 8 + j]);

#pragma unroll
    for (int i = 0; i < 8; i++) {
        int w = ty * 8 + i;
        float* op = out + ((size_t)(b * HH + h) * WW + w) * FF + tx * 8;
        float4 o0 = make_float4(acc[i][0] + bv[0], acc[i][1] + bv[1],
                                acc[i][2] + bv[2], acc[i][3] + bv[3]);
        float4 o1 = make_float4(acc[i][4] + bv[4], acc[i][5] + bv[5],
                                acc[i][6] + bv[6], acc[i][7] + bv[7]);
        *(float4*)(op + 0) = o0;
        *(float4*)(op + 4) = o1;
    }
}

// ---------------------------------------------------------------------------
extern "C" void kernel_launch(void* const* d_in, const int* in_sizes, int n_in,
                              void* d_out, int out_size)
{
    const float* x    = (const float*)d_in[0];  // (8,128,128,64)
    const float* Woff = (const float*)d_in[1];  // (3,3,64,18)
    const float* boff = (const float*)d_in[2];  // (18,)
    const float* Wt   = (const float*)d_in[3];  // (3,3,576,128)
    const float* bias = (const float*)d_in[4];  // (128,)
    float* out = (float*)d_out;                 // (8,128,128,128)

    offset_conv_kernel<<<NPIX / 256, 256>>>(x, Woff, boff);
    sample_kernel<<<(NPIX * KT) / 8, 256>>>(x);
    final_conv_kernel<<<BB * HH, 256>>>(Wt, bias, out);
}

// round 3
// speedup vs baseline: 2.2622x; 2.2622x over previous
#include <cuda_runtime.h>
#include <cuda_bf16.h>
#include <cstdint>
#include <cstddef>

#define BB 8
#define HH 128
#define WW 128
#define CC 64
#define FF 128
#define KT 9            // K*K taps
#define OC 18           // 2*KT offset channels
#define SC 576          // KT*CC sampled channels
#define KTOT (KT*SC)    // 5184 total GEMM K
#define NPIX (BB*HH*WW) // 131072

// Scratch (allocation-free rule: __device__ globals)
__device__ float         g_offsets[(size_t)NPIX * OC];   // ~9.4 MB
__device__ __nv_bfloat16 g_shi[(size_t)NPIX * SC];       // 151 MB
__device__ __nv_bfloat16 g_slo[(size_t)NPIX * SC];       // 151 MB
__device__ __nv_bfloat16 g_whi[(size_t)FF * KTOT];       // 1.33 MB [f][k]
__device__ __nv_bfloat16 g_wlo[(size_t)FF * KTOT];       // 1.33 MB

// ---------------------------------------------------------------------------
// helpers (all sm_80-era PTX — legal under compute_103)
// ---------------------------------------------------------------------------
__device__ __forceinline__ void cpa16(uint32_t dst, const void* src, int sz) {
    asm volatile("cp.async.cg.shared.global [%0], [%1], 16, %2;"
                 :: "r"(dst), "l"(src), "r"(sz));
}
__device__ __forceinline__ void cpa_commit() {
    asm volatile("cp.async.commit_group;" ::: "memory");
}
template <int N> __device__ __forceinline__ void cpa_wait() {
    asm volatile("cp.async.wait_group %0;" :: "n"(N) : "memory");
}
__device__ __forceinline__ void ldsm4(uint32_t* r, uint32_t addr) {
    asm volatile("ldmatrix.sync.aligned.m8n8.x4.shared.b16 {%0,%1,%2,%3}, [%4];"
                 : "=r"(r[0]), "=r"(r[1]), "=r"(r[2]), "=r"(r[3]) : "r"(addr));
}
__device__ __forceinline__ void mma16816(float* d, const uint32_t* a,
                                         uint32_t b0, uint32_t b1) {
    asm volatile(
        "mma.sync.aligned.m16n8k16.row.col.f32.bf16.bf16.f32 "
        "{%0,%1,%2,%3}, {%4,%5,%6,%7}, {%8,%9}, {%0,%1,%2,%3};"
        : "+f"(d[0]), "+f"(d[1]), "+f"(d[2]), "+f"(d[3])
        : "r"(a[0]), "r"(a[1]), "r"(a[2]), "r"(a[3]), "r"(b0), "r"(b1));
}
__device__ __forceinline__ void split_bf16(float v, __nv_bfloat16& hi, __nv_bfloat16& lo) {
    hi = __float2bfloat16(v);
    lo = __float2bfloat16(v - __bfloat162float(hi));
}
__device__ __forceinline__ uint32_t swz(uint32_t off) {
    return off ^ ((off >> 3) & 0x70u);
}

// ---------------------------------------------------------------------------
// Kernel 0: weight transpose + bf16 hi/lo split.  Wt (3,3,576,128) -> [f][k]
// ---------------------------------------------------------------------------
__global__ __launch_bounds__(256) void wprep_kernel(const float* __restrict__ Wt)
{
    int idx = blockIdx.x * 256 + threadIdx.x;     // over FF*KTOT = 663552
    if (idx >= FF * KTOT) return;
    int kk = idx >> 7;
    int f  = idx & 127;
    float v = Wt[idx];
    __nv_bfloat16 hi, lo; split_bf16(v, hi, lo);
    g_whi[(size_t)f * KTOT + kk] = hi;
    g_wlo[(size_t)f * KTOT + kk] = lo;
}

// ---------------------------------------------------------------------------
// Kernel 1: offset conv  (3x3, C=64 -> 18, SAME padding)
// ---------------------------------------------------------------------------
__global__ __launch_bounds__(256) void offset_conv_kernel(
    const float* __restrict__ x, const float* __restrict__ Woff,
    const float* __restrict__ boff)
{
    __shared__ float sW[3 * 3 * CC * OC];
    __shared__ float sB[OC];
    int tid = threadIdx.x;
    for (int i = tid; i < 3 * 3 * CC * OC; i += 256) sW[i] = Woff[i];
    if (tid < OC) sB[tid] = boff[tid];
    __syncthreads();

    int p = blockIdx.x * 256 + tid;
    int b = p >> 14;
    int h = (p >> 7) & 127;
    int w = p & 127;

    float acc[OC];
#pragma unroll
    for (int o = 0; o < OC; o++) acc[o] = sB[o];

    for (int ky = 0; ky < 3; ky++) {
        int y = h + ky - 1;
        if ((unsigned)y >= HH) continue;
        for (int kx = 0; kx < 3; kx++) {
            int xx = w + kx - 1;
            if ((unsigned)xx >= WW) continue;
            const float* xp = x + (((size_t)(b * HH + y) * WW + xx) * CC);
            const float* wp = sW + (ky * 3 + kx) * CC * OC;
            for (int c = 0; c < CC; c += 4) {
                float4 v = *(const float4*)(xp + c);
#pragma unroll
                for (int o = 0; o < OC; o++) {
                    acc[o] += v.x * wp[(c + 0) * OC + o]
                            + v.y * wp[(c + 1) * OC + o]
                            + v.z * wp[(c + 2) * OC + o]
                            + v.w * wp[(c + 3) * OC + o];
                }
            }
        }
    }
    float* op = g_offsets + (size_t)p * OC;
#pragma unroll
    for (int o = 0; o < OC; o++) op[o] = acc[o];
}

// ---------------------------------------------------------------------------
// Kernel 2: bilinear deformable sampling -> bf16 hi/lo planes
// ---------------------------------------------------------------------------
__global__ __launch_bounds__(256) void sample_kernel(const float* __restrict__ x)
{
    int gw = blockIdx.x * 8 + (threadIdx.x >> 5);
    int lane = threadIdx.x & 31;
    int p = gw / KT;
    int tap = gw - p * KT;
    if (p >= NPIX) return;

    int b = p >> 14;
    int h = (p >> 7) & 127;
    int w = p & 127;

    float offx = __ldg(&g_offsets[(size_t)p * OC + tap * 2 + 0]);
    float offy = __ldg(&g_offsets[(size_t)p * OC + tap * 2 + 1]);

    float lx = (float)w + (float)(tap % 3) - 1.0f + offx;
    float ly = (float)h + (float)(tap / 3) - 1.0f + offy;
    lx = fminf(fmaxf(lx, 0.0f), (float)(WW - 1));
    ly = fminf(fmaxf(ly, 0.0f), (float)(HH - 1));

    float x0f = floorf(lx);
    float y0f = floorf(ly);
    float x1f = fminf(x0f + 1.0f, (float)(WW - 1));
    float y1f = fminf(y0f + 1.0f, (float)(HH - 1));

    float wa = (x1f - lx) * (y1f - ly);
    float wb = (x1f - lx) * (ly - y0f);
    float wc = (lx - x0f) * (y1f - ly);
    float wd = (lx - x0f) * (ly - y0f);

    int x0 = (int)x0f, x1 = (int)x1f, y0 = (int)y0f, y1 = (int)y1f;

    int c = lane * 2;
    const float* xb = x + (size_t)b * HH * WW * CC + c;
    float2 Ia = *(const float2*)(xb + ((size_t)y0 * WW + x0) * CC);
    float2 Ib = *(const float2*)(xb + ((size_t)y1 * WW + x0) * CC);
    float2 Ic = *(const float2*)(xb + ((size_t)y0 * WW + x1) * CC);
    float2 Id = *(const float2*)(xb + ((size_t)y1 * WW + x1) * CC);

    float sx = wa * Ia.x + wb * Ib.x + wc * Ic.x + wd * Id.x;
    float sy = wa * Ia.y + wb * Ib.y + wc * Ic.y + wd * Id.y;

    __nv_bfloat16 hx, lx2, hy, ly2;
    split_bf16(sx, hx, lx2);
    split_bf16(sy, hy, ly2);

    size_t o = (size_t)p * SC + tap * CC + c;
    __nv_bfloat162 h2; h2.x = hx; h2.y = hy;
    __nv_bfloat162 l2; l2.x = lx2; l2.y = ly2;
    *(__nv_bfloat162*)(g_shi + o) = h2;
    *(__nv_bfloat162*)(g_slo + o) = l2;
}

// ---------------------------------------------------------------------------
// Kernel 3: final conv as bf16x3 HMMA GEMM (mma.sync.m16n8k16).
// One CTA per (b,h): D[128 px][128 f], K=5184 in 81 chunks of 64.
// 3-stage cp.async pipeline; SW128-style XOR swizzle; 8 warps, 64x32 warp tile.
// ---------------------------------------------------------------------------
#define TILEB 16384
#define STAGEB (4 * TILEB)       // Ahi | Alo | Bhi | Blo
#define DSMEM  (3 * STAGEB + 1024)

__device__ __forceinline__ void load_chunk(int c, uint32_t base, int b, int h, int tid)
{
    int seg = c / 9;
    int kc  = (c - seg * 9) * 64;
    int ky = seg / 3, kx = seg - ky * 3;
    int y = h + ky - 1;
    bool yok = (unsigned)y < (unsigned)HH;
    int yc = yok ? y : 0;
    int q  = tid & 7;          // 16B chunk within 128B row
    int rb = tid >> 3;         // row base 0..31

    size_t abase = (size_t)((b * HH + yc) * WW) * SC + kc + q * 8;
    const __nv_bfloat16* wh = g_whi + (size_t)(seg * SC + kc) + q * 8;
    const __nv_bfloat16* wl = g_wlo + (size_t)(seg * SC + kc) + q * 8;

#pragma unroll
    for (int i = 0; i < 4; i++) {
        int m = i * 32 + rb;
        int ws = m + kx - 1;
        bool ok = yok && ((unsigned)ws < (unsigned)WW);
        size_t src = abase + (size_t)(ok ? ws : 0) * SC;
        uint32_t off = swz((uint32_t)(m * 128 + q * 16));
        int sz = ok ? 16 : 0;
        cpa16(base + off,         g_shi + src, sz);
        cpa16(base + TILEB + off, g_slo + src, sz);
    }
#pragma unroll
    for (int i = 0; i < 4; i++) {
        int f = i * 32 + rb;
        uint32_t off = swz((uint32_t)(f * 128 + q * 16));
        cpa16(base + 2 * TILEB + off, wh + (size_t)f * KTOT, 16);
        cpa16(base + 3 * TILEB + off, wl + (size_t)f * KTOT, 16);
    }
}

__global__ __launch_bounds__(256) void final_conv_mma(
    const float* __restrict__ bias, float* __restrict__ out)
{
    extern __shared__ char dsm[];
    __shared__ float sbias[FF];
    uint32_t tb = ((uint32_t)__cvta_generic_to_shared(dsm) + 1023) & ~1023u;
    int tid = threadIdx.x, wid = tid >> 5, l = tid & 31;
    int row = blockIdx.x, b = row >> 7, h = row & 127;

    if (tid < FF) sbias[tid] = bias[tid];

    int mw = (wid & 1) * 64;     // warp M offset (0/64)
    int nw = (wid >> 1) * 32;    // warp N offset (0/32/64/96)
    int lr = l & 15, lc = l >> 4;

    // ldmatrix lane base offsets (swizzled); per-kstep address = base ^ (ks*32)
    uint32_t aoff = swz((uint32_t)((mw + lr) * 128 + lc * 16));
    uint32_t boff = swz((uint32_t)((nw + lr) * 128 + lc * 16));

    float acc[4][4][4];
#pragma unroll
    for (int i = 0; i < 4; i++)
#pragma unroll
        for (int j = 0; j < 4; j++)
#pragma unroll
            for (int k = 0; k < 4; k++) acc[i][j][k] = 0.0f;

    load_chunk(0, tb + 0 * STAGEB, b, h, tid); cpa_commit();
    load_chunk(1, tb + 1 * STAGEB, b, h, tid); cpa_commit();

    for (int c = 0; c < 81; c++) {
        int s = c - (c / 3) * 3;
        if (c < 80) cpa_wait<1>(); else cpa_wait<0>();
        __syncthreads();

        if (c + 2 < 81) {
            int sp = (c + 2) - ((c + 2) / 3) * 3;
            load_chunk(c + 2, tb + sp * STAGEB, b, h, tid);
            cpa_commit();
        }

        uint32_t Ah = tb + s * STAGEB;
        uint32_t Al = Ah + TILEB;
        uint32_t Bh = Ah + 2 * TILEB;
        uint32_t Bl = Ah + 3 * TILEB;

#pragma unroll
        for (int ks = 0; ks < 4; ks++) {
            uint32_t dk = (uint32_t)(ks * 32);
            uint32_t ahr[4][4], alr[4][4], bhr[2][4], blr[2][4];
#pragma unroll
            for (int mf = 0; mf < 4; mf++) {
                ldsm4(ahr[mf], Ah + mf * 2048 + (aoff ^ dk));
                ldsm4(alr[mf], Al + mf * 2048 + (aoff ^ dk));
            }
#pragma unroll
            for (int nb = 0; nb < 2; nb++) {
                ldsm4(bhr[nb], Bh + nb * 2048 + (boff ^ dk));
                ldsm4(blr[nb], Bl + nb * 2048 + (boff ^ dk));
            }
#pragma unroll
            for (int mf = 0; mf < 4; mf++) {
#pragma unroll
                for (int nf = 0; nf < 4; nf++) {
                    int nb = nf >> 1, hi = nf & 1;
                    mma16816(acc[mf][nf], ahr[mf], bhr[nb][hi], bhr[nb][hi + 2]);
                    mma16816(acc[mf][nf], ahr[mf], blr[nb][hi], blr[nb][hi + 2]);
                    mma16816(acc[mf][nf], alr[mf], bhr[nb][hi], bhr[nb][hi + 2]);
                }
            }
        }
    }

    // epilogue: c-frag lane mapping: (m = mf*16 + l/4 (+8), n = nf*8 + 2*(l%4))
#pragma unroll
    for (int mf = 0; mf < 4; mf++) {
#pragma unroll
        for (int nf = 0; nf < 4; nf++) {
            int m = mw + mf * 16 + (l >> 2);
            int n = nw + nf * 8 + (l & 3) * 2;
            float bx = sbias[n], by = sbias[n + 1];
            float* o0 = out + ((size_t)row * 128 + m) * FF + n;
            float* o1 = o0 + 8 * FF;
            float2 v0 = make_float2(acc[mf][nf][0] + bx, acc[mf][nf][1] + by);
            float2 v1 = make_float2(acc[mf][nf][2] + bx, acc[mf][nf][3] + by);
            *(float2*)o0 = v0;
            *(float2*)o1 = v1;
        }
    }
}

// ---------------------------------------------------------------------------
extern "C" void kernel_launch(void* const* d_in, const int* in_sizes, int n_in,
                              void* d_out, int out_size)
{
    const float* x    = (const float*)d_in[0];  // (8,128,128,64)
    const float* Woff = (const float*)d_in[1];  // (3,3,64,18)
    const float* boff = (const float*)d_in[2];  // (18,)
    const float* Wt   = (const float*)d_in[3];  // (3,3,576,128)
    const float* bias = (const float*)d_in[4];  // (128,)
    float* out = (float*)d_out;                 // (8,128,128,128)

    cudaFuncSetAttribute(final_conv_mma,
                         cudaFuncAttributeMaxDynamicSharedMemorySize, DSMEM);

    wprep_kernel<<<(FF * KTOT + 255) / 256, 256>>>(Wt);
    offset_conv_kernel<<<NPIX / 256, 256>>>(x, Woff, boff);
    sample_kernel<<<(NPIX * KT) / 8, 256>>>(x);
    final_conv_mma<<<BB * HH, 256, DSMEM>>>(bias, out);
}

// round 4
// speedup vs baseline: 3.0772x; 1.3603x over previous
#include <cuda_runtime.h>
#include <cuda_bf16.h>
#include <cstdint>
#include <cstddef>

#define BB 8
#define HH 128
#define WW 128
#define CC 64
#define FF 128
#define KT 9            // K*K taps
#define OC 18           // 2*KT offset channels
#define SC 576          // KT*CC sampled channels
#define KTOT (KT*SC)    // 5184 total GEMM K
#define NPIX (BB*HH*WW) // 131072

// Scratch (allocation-free rule: __device__ globals)
__device__ float g_offsets[(size_t)NPIX * OC];   // ~9.4 MB
__device__ float g_s[(size_t)NPIX * SC];         // 302 MB (tf32-rounded fp32)
__device__ float g_w[(size_t)FF * KTOT];         // 2.65 MB [f][k] (tf32-rounded)

// ---------------------------------------------------------------------------
// helpers (all sm_80-era PTX — legal under compute_103)
// ---------------------------------------------------------------------------
__device__ __forceinline__ void cpa16(uint32_t dst, const void* src, int sz) {
    asm volatile("cp.async.cg.shared.global [%0], [%1], 16, %2;"
                 :: "r"(dst), "l"(src), "r"(sz));
}
__device__ __forceinline__ void cpa_commit() {
    asm volatile("cp.async.commit_group;" ::: "memory");
}
template <int N> __device__ __forceinline__ void cpa_wait() {
    asm volatile("cp.async.wait_group %0;" :: "n"(N) : "memory");
}
__device__ __forceinline__ void ldsm4(uint32_t* r, uint32_t addr) {
    asm volatile("ldmatrix.sync.aligned.m8n8.x4.shared.b16 {%0,%1,%2,%3}, [%4];"
                 : "=r"(r[0]), "=r"(r[1]), "=r"(r[2]), "=r"(r[3]) : "r"(addr));
}
__device__ __forceinline__ void mma_tf32(float* d, const uint32_t* a,
                                         uint32_t b0, uint32_t b1) {
    asm volatile(
        "mma.sync.aligned.m16n8k8.row.col.f32.tf32.tf32.f32 "
        "{%0,%1,%2,%3}, {%4,%5,%6,%7}, {%8,%9}, {%0,%1,%2,%3};"
        : "+f"(d[0]), "+f"(d[1]), "+f"(d[2]), "+f"(d[3])
        : "r"(a[0]), "r"(a[1]), "r"(a[2]), "r"(a[3]), "r"(b0), "r"(b1));
}
__device__ __forceinline__ float tf32r(float v) {
    uint32_t u;
    asm("cvt.rna.tf32.f32 %0, %1;" : "=r"(u) : "f"(v));
    return __uint_as_float(u);
}
__device__ __forceinline__ uint32_t swz(uint32_t off) {
    return off ^ ((off >> 3) & 0x70u);
}

// ---------------------------------------------------------------------------
// Kernel 0: weight transpose + tf32 round.  Wt (3,3,576,128) -> g_w[f][k]
// ---------------------------------------------------------------------------
__global__ __launch_bounds__(256) void wprep_kernel(const float* __restrict__ Wt)
{
    int idx = blockIdx.x * 256 + threadIdx.x;     // over FF*KTOT = 663552
    if (idx >= FF * KTOT) return;
    int kk = idx >> 7;
    int f  = idx & 127;
    g_w[(size_t)f * KTOT + kk] = tf32r(Wt[idx]);
}

// ---------------------------------------------------------------------------
// Kernel 1: offset conv  (3x3, C=64 -> 18, SAME padding)
// ---------------------------------------------------------------------------
__global__ __launch_bounds__(256) void offset_conv_kernel(
    const float* __restrict__ x, const float* __restrict__ Woff,
    const float* __restrict__ boff)
{
    __shared__ float sW[3 * 3 * CC * OC];
    __shared__ float sB[OC];
    int tid = threadIdx.x;
    for (int i = tid; i < 3 * 3 * CC * OC; i += 256) sW[i] = Woff[i];
    if (tid < OC) sB[tid] = boff[tid];
    __syncthreads();

    int p = blockIdx.x * 256 + tid;
    int b = p >> 14;
    int h = (p >> 7) & 127;
    int w = p & 127;

    float acc[OC];
#pragma unroll
    for (int o = 0; o < OC; o++) acc[o] = sB[o];

    for (int ky = 0; ky < 3; ky++) {
        int y = h + ky - 1;
        if ((unsigned)y >= HH) continue;
        for (int kx = 0; kx < 3; kx++) {
            int xx = w + kx - 1;
            if ((unsigned)xx >= WW) continue;
            const float* xp = x + (((size_t)(b * HH + y) * WW + xx) * CC);
            const float* wp = sW + (ky * 3 + kx) * CC * OC;
            for (int c = 0; c < CC; c += 4) {
                float4 v = *(const float4*)(xp + c);
#pragma unroll
                for (int o = 0; o < OC; o++) {
                    acc[o] += v.x * wp[(c + 0) * OC + o]
                            + v.y * wp[(c + 1) * OC + o]
                            + v.z * wp[(c + 2) * OC + o]
                            + v.w * wp[(c + 3) * OC + o];
                }
            }
        }
    }
    float* op = g_offsets + (size_t)p * OC;
#pragma unroll
    for (int o = 0; o < OC; o++) op[o] = acc[o];
}

// ---------------------------------------------------------------------------
// Kernel 2: bilinear deformable sampling -> tf32-rounded fp32 plane
// ---------------------------------------------------------------------------
__global__ __launch_bounds__(256) void sample_kernel(const float* __restrict__ x)
{
    int gw = blockIdx.x * 8 + (threadIdx.x >> 5);
    int lane = threadIdx.x & 31;
    int p = gw / KT;
    int tap = gw - p * KT;
    if (p >= NPIX) return;

    int b = p >> 14;
    int h = (p >> 7) & 127;
    int w = p & 127;

    float offx = __ldg(&g_offsets[(size_t)p * OC + tap * 2 + 0]);
    float offy = __ldg(&g_offsets[(size_t)p * OC + tap * 2 + 1]);

    float lx = (float)w + (float)(tap % 3) - 1.0f + offx;
    float ly = (float)h + (float)(tap / 3) - 1.0f + offy;
    lx = fminf(fmaxf(lx, 0.0f), (float)(WW - 1));
    ly = fminf(fmaxf(ly, 0.0f), (float)(HH - 1));

    float x0f = floorf(lx);
    float y0f = floorf(ly);
    float x1f = fminf(x0f + 1.0f, (float)(WW - 1));
    float y1f = fminf(y0f + 1.0f, (float)(HH - 1));

    float wa = (x1f - lx) * (y1f - ly);
    float wb = (x1f - lx) * (ly - y0f);
    float wc = (lx - x0f) * (y1f - ly);
    float wd = (lx - x0f) * (ly - y0f);

    int x0 = (int)x0f, x1 = (int)x1f, y0 = (int)y0f, y1 = (int)y1f;

    int c = lane * 2;
    const float* xb = x + (size_t)b * HH * WW * CC + c;
    float2 Ia = *(const float2*)(xb + ((size_t)y0 * WW + x0) * CC);
    float2 Ib = *(const float2*)(xb + ((size_t)y1 * WW + x0) * CC);
    float2 Ic = *(const float2*)(xb + ((size_t)y0 * WW + x1) * CC);
    float2 Id = *(const float2*)(xb + ((size_t)y1 * WW + x1) * CC);

    float sx = wa * Ia.x + wb * Ib.x + wc * Ic.x + wd * Id.x;
    float sy = wa * Ia.y + wb * Ib.y + wc * Ic.y + wd * Id.y;

    float2 s2 = make_float2(tf32r(sx), tf32r(sy));
    *(float2*)(g_s + (size_t)p * SC + tap * CC + c) = s2;
}

// ---------------------------------------------------------------------------
// Kernel 3: final conv as tf32 HMMA GEMM (mma.sync.m16n8k8).
// One CTA per (b,h): D[128 px][128 f], K=5184 in 162 chunks of 32.
// 3-stage cp.async pipeline, 32KB/stage (96KB total) -> 2 CTAs/SM.
// ---------------------------------------------------------------------------
#define TILEB 16384                  // one operand tile: 128 rows x 128B
#define STAGEB (2 * TILEB)           // A | B
#define DSMEM  (3 * STAGEB + 1024)

__device__ __forceinline__ void load_chunk(int c, uint32_t base, int b, int h, int tid)
{
    int seg = c / 18;                // conv tap segment 0..8
    int kc  = (c - seg * 18) * 32;   // fp32 offset within 576
    int ky = seg / 3, kx = seg - ky * 3;
    int y = h + ky - 1;
    bool yok = (unsigned)y < (unsigned)HH;
    int yc = yok ? y : 0;
    int q  = tid & 7;                // 16B unit within 128B row
    int rb = tid >> 3;               // row 0..31

    size_t abase = (size_t)((b * HH + yc) * WW) * SC + kc + q * 4;
    const float* wsrc = g_w + (size_t)(seg * SC + kc) + q * 4;

#pragma unroll
    for (int i = 0; i < 4; i++) {
        int m = i * 32 + rb;
        int ws = m + kx - 1;
        bool ok = yok && ((unsigned)ws < (unsigned)WW);
        const float* src = g_s + abase + (size_t)(ok ? ws : 0) * SC;
        uint32_t off = swz((uint32_t)(m * 128 + q * 16));
        cpa16(base + off, src, ok ? 16 : 0);
    }
#pragma unroll
    for (int i = 0; i < 4; i++) {
        int f = i * 32 + rb;
        uint32_t off = swz((uint32_t)(f * 128 + q * 16));
        cpa16(base + TILEB + off, wsrc + (size_t)f * KTOT, 16);
    }
}

__global__ __launch_bounds__(256, 2) void final_conv_mma(
    const float* __restrict__ bias, float* __restrict__ out)
{
    extern __shared__ char dsm[];
    __shared__ float sbias[FF];
    uint32_t tb = ((uint32_t)__cvta_generic_to_shared(dsm) + 1023) & ~1023u;
    int tid = threadIdx.x, wid = tid >> 5, l = tid & 31;
    int row = blockIdx.x, b = row >> 7, h = row & 127;

    if (tid < FF) sbias[tid] = bias[tid];

    int mw = (wid & 1) * 64;     // warp M offset (0/64)
    int nw = (wid >> 1) * 32;    // warp N offset (0/32/64/96)
    int lr = l & 15, lc = l >> 4;

    // ldmatrix lane base offsets (swizzled); per-kstep address = base ^ (ks*32)
    uint32_t aoff = swz((uint32_t)((mw + lr) * 128 + lc * 16));
    uint32_t boff = swz((uint32_t)((nw + lr) * 128 + lc * 16));

    float acc[4][4][4];
#pragma unroll
    for (int i = 0; i < 4; i++)
#pragma unroll
        for (int j = 0; j < 4; j++)
#pragma unroll
            for (int k = 0; k < 4; k++) acc[i][j][k] = 0.0f;

    load_chunk(0, tb + 0 * STAGEB, b, h, tid); cpa_commit();
    load_chunk(1, tb + 1 * STAGEB, b, h, tid); cpa_commit();

    for (int c = 0; c < 162; c++) {
        int s = c - (c / 3) * 3;
        if (c < 161) cpa_wait<1>(); else cpa_wait<0>();
        __syncthreads();

        if (c + 2 < 162) {
            int sp = (c + 2) - ((c + 2) / 3) * 3;
            load_chunk(c + 2, tb + sp * STAGEB, b, h, tid);
            cpa_commit();
        }

        uint32_t Ast = tb + s * STAGEB;
        uint32_t Bst = Ast + TILEB;

#pragma unroll
        for (int ks = 0; ks < 4; ks++) {          // 4 k-steps of k=8 tf32
            uint32_t dk = (uint32_t)(ks * 32);
            uint32_t ar[4][4], br[2][4];
#pragma unroll
            for (int mf = 0; mf < 4; mf++)
                ldsm4(ar[mf], Ast + mf * 2048 + (aoff ^ dk));
#pragma unroll
            for (int nb = 0; nb < 2; nb++)
                ldsm4(br[nb], Bst + nb * 2048 + (boff ^ dk));
#pragma unroll
            for (int mf = 0; mf < 4; mf++) {
#pragma unroll
                for (int nf = 0; nf < 4; nf++) {
                    int nb = nf >> 1, hi = nf & 1;
                    mma_tf32(acc[mf][nf], ar[mf], br[nb][hi], br[nb][hi + 2]);
                }
            }
        }
    }

    // epilogue: c-frag lane mapping: (m = mf*16 + l/4 (+8), n = nf*8 + 2*(l%4))
#pragma unroll
    for (int mf = 0; mf < 4; mf++) {
#pragma unroll
        for (int nf = 0; nf < 4; nf++) {
            int m = mw + mf * 16 + (l >> 2);
            int n = nw + nf * 8 + (l & 3) * 2;
            float bx = sbias[n], by = sbias[n + 1];
            float* o0 = out + ((size_t)row * 128 + m) * FF + n;
            float* o1 = o0 + 8 * FF;
            float2 v0 = make_float2(acc[mf][nf][0] + bx, acc[mf][nf][1] + by);
            float2 v1 = make_float2(acc[mf][nf][2] + bx, acc[mf][nf][3] + by);
            *(float2*)o0 = v0;
            *(float2*)o1 = v1;
        }
    }
}

// ---------------------------------------------------------------------------
extern "C" void kernel_launch(void* const* d_in, const int* in_sizes, int n_in,
                              void* d_out, int out_size)
{
    const float* x    = (const float*)d_in[0];  // (8,128,128,64)
    const float* Woff = (const float*)d_in[1];  // (3,3,64,18)
    const float* boff = (const float*)d_in[2];  // (18,)
    const float* Wt   = (const float*)d_in[3];  // (3,3,576,128)
    const float* bias = (const float*)d_in[4];  // (128,)
    float* out = (float*)d_out;                 // (8,128,128,128)

    cudaFuncSetAttribute(final_conv_mma,
                         cudaFuncAttributeMaxDynamicSharedMemorySize, DSMEM);

    wprep_kernel<<<(FF * KTOT + 255) / 256, 256>>>(Wt);
    offset_conv_kernel<<<NPIX / 256, 256>>>(x, Woff, boff);
    sample_kernel<<<(NPIX * KT) / 8, 256>>>(x);
    final_conv_mma<<<BB * HH, 256, DSMEM>>>(bias, out);
}